// round 16
// baseline (speedup 1.0000x reference)
#include <cuda_runtime.h>
#include <cstdint>
#include <cstddef>

// ---------------- problem constants ----------------
#define BB 512
#define TT 128
#define II 64
#define HH 512
#define OO 64
#define LMAX 300
#define KENC 576   // [h(512) | x(64)]
#define KDEC 512

#define NCTA 128   // persistent grid size (8 x 16)

// ---------------- device scratch ----------------
__device__ float g_h[2][BB * HH];                   // fp32 encoder ping-pong
__device__ float g_hist[(size_t)LMAX * BB * HH];    // fp32 decoder hidden history
__device__ uint2 g_hs0[BB * HH / 2];                // split-h ping-pong (bf16 hi|lo pairs)
__device__ uint2 g_hs1[BB * HH / 2];
__device__ uint2 g_Wdec_s[4 * HH * KDEC / 2];
__device__ uint2 g_Wenc_s[4 * HH * KENC / 2];
__device__ uint2 g_xs[(size_t)BB * TT * II / 2];
__device__ float g_bdec[4 * HH];
__device__ float g_benc[4 * HH];
__device__ unsigned g_bar;                          // grid barrier (zeroed every launch)

// ---------------- helpers ----------------
__device__ __forceinline__ float sigmoidf_(float x) { return 1.0f / (1.0f + __expf(-x)); }

__device__ __forceinline__ uint2 split2(float v0, float v1) {
    uint32_t hi;
    asm("cvt.rn.bf16x2.f32 %0, %1, %2;" : "=r"(hi) : "f"(v1), "f"(v0));
    float h0 = __uint_as_float(hi << 16);
    float h1 = __uint_as_float(hi & 0xFFFF0000u);
    uint32_t lo;
    asm("cvt.rn.bf16x2.f32 %0, %1, %2;" : "=r"(lo) : "f"(v1 - h1), "f"(v0 - h0));
    return make_uint2(hi, lo);
}

__device__ __forceinline__ void mmab(float d[4], uint32_t a0, uint32_t a1, uint32_t a2,
                                     uint32_t a3, uint32_t b0, uint32_t b1) {
    asm volatile(
        "mma.sync.aligned.m16n8k16.row.col.f32.bf16.bf16.f32 "
        "{%0,%1,%2,%3},{%4,%5,%6,%7},{%8,%9},{%0,%1,%2,%3};"
        : "+f"(d[0]), "+f"(d[1]), "+f"(d[2]), "+f"(d[3])
        : "r"(a0), "r"(a1), "r"(a2), "r"(a3), "r"(b0), "r"(b1));
}

__device__ __forceinline__ void cp16(uint32_t saddr, const void* gaddr) {
    asm volatile("cp.async.cg.shared.global [%0], [%1], 16;"
                 :: "r"(saddr), "l"(gaddr) : "memory");
}
__device__ __forceinline__ uint32_t smem_u32_(const void* p) {
    uint32_t a;
    asm("{ .reg .u64 t; cvta.to.shared.u64 t, %1; cvt.u32.u64 %0, t; }" : "=r"(a) : "l"(p));
    return a;
}

// ---------------- prep kernels ----------------
__global__ void k_zero_h0() {
    int i = blockIdx.x * blockDim.x + threadIdx.x;
    if (i < BB * HH) g_h[0][i] = 0.0f;
    if (i < BB * HH / 2) g_hs0[i] = make_uint2(0u, 0u);
    if (i == 0) g_bar = 0u;
}

__global__ void k_prep_dec(const float* __restrict__ Whh, const float* __restrict__ Wih,
                           const float* __restrict__ Wo) {
    int idx = blockIdx.x * blockDim.x + threadIdx.x;
    if (idx >= 4 * HH * (KDEC / 2)) return;
    int row = idx / (KDEC / 2);
    int kp = idx % (KDEC / 2);
    float v[2];
    #pragma unroll
    for (int e = 0; e < 2; ++e) {
        int k = 2 * kp + e;
        if (row < 3 * HH) {
            float s = 0.0f;
            const float* wr = Wih + (size_t)row * II;
            #pragma unroll 8
            for (int o = 0; o < II; ++o) s += wr[o] * Wo[(size_t)o * HH + k];
            v[e] = (row < 2 * HH) ? (Whh[(size_t)row * HH + k] + s) : s;
        } else {
            v[e] = Whh[(size_t)(row - HH) * HH + k];
        }
    }
    g_Wdec_s[idx] = split2(v[0], v[1]);
}

__global__ void k_prep_enc(const float* __restrict__ Whh, const float* __restrict__ Wih) {
    int idx = blockIdx.x * blockDim.x + threadIdx.x;
    if (idx >= 4 * HH * (KENC / 2)) return;
    int row = idx / (KENC / 2);
    int kp = idx % (KENC / 2);
    int g = row >> 9, j = row & (HH - 1);
    float v[2];
    #pragma unroll
    for (int e = 0; e < 2; ++e) {
        int k = 2 * kp + e;
        float val = 0.0f;
        if (g == 0) val = (k < HH) ? Whh[(size_t)j * HH + k]            : Wih[(size_t)j * II + (k - HH)];
        if (g == 1) val = (k < HH) ? Whh[(size_t)(HH + j) * HH + k]     : Wih[(size_t)(HH + j) * II + (k - HH)];
        if (g == 2) val = (k < HH) ? 0.0f                               : Wih[(size_t)(2 * HH + j) * II + (k - HH)];
        if (g == 3) val = (k < HH) ? Whh[(size_t)(2 * HH + j) * HH + k] : 0.0f;
        v[e] = val;
    }
    g_Wenc_s[idx] = split2(v[0], v[1]);
}

__global__ void k_prep_x(const float* __restrict__ input) {
    size_t idx = (size_t)blockIdx.x * blockDim.x + threadIdx.x;
    if (idx >= (size_t)BB * TT * II / 2) return;
    g_xs[idx] = split2(input[2 * idx], input[2 * idx + 1]);
}

__global__ void k_prep_bias(const float* __restrict__ bih, const float* __restrict__ bhh,
                            const float* __restrict__ Wih, const float* __restrict__ bo) {
    int idx = blockIdx.x * blockDim.x + threadIdx.x;
    if (idx >= 4 * HH) return;
    int g = idx >> 9, j = idx & (HH - 1);
    float be;
    if (g == 0) be = bih[j] + bhh[j];
    else if (g == 1) be = bih[HH + j] + bhh[HH + j];
    else if (g == 2) be = bih[2 * HH + j];
    else be = bhh[2 * HH + j];
    g_benc[idx] = be;
    float bd;
    if (g < 3) {
        int r = g * HH + j;
        float s = 0.0f;
        const float* wr = Wih + (size_t)r * II;
        #pragma unroll 8
        for (int o = 0; o < II; ++o) s += wr[o] * bo[o];
        bd = bih[r] + s + ((g < 2) ? bhh[r] : 0.0f);
    } else {
        bd = bhh[2 * HH + j];
    }
    g_bdec[idx] = bd;
}

// ---------------- persistent fused GRU ----------------
// grid (8, 16) = 128 CTAs, 1/SM. CTA tile 64 batch x (4 gates x 32 j).
// 3-stage cp.async pipeline; warp-staggered ks order (crossbar/tensor overlap);
// term-major mma (same-acc distance 8); release/acquire grid barrier.
#define STEP_THREADS 256
#define SPITCH 20                                      // u64 per smem row
#define ROWS_BUF 192                                   // 64 A rows + 128 B rows
#define BUF_U64 (ROWS_BUF * SPITCH)
#define SMEM_BYTES (3 * BUF_U64 * 8)                   // 92160

__global__ __launch_bounds__(STEP_THREADS, 1) void k_gru(int L) {
    extern __shared__ __align__(16) uint2 sm[];        // [3][192][SPITCH]

    const int tid = threadIdx.x, lane = tid & 31, wid = tid >> 5;
    const int wm = wid >> 2, jb = wid & 3;
    const int m0 = blockIdx.x * 64, j0 = blockIdx.y * 32;
    const int lr = lane >> 2, lc = lane & 3;
    const uint32_t sbase = smem_u32_(sm);

    const int arow = (tid >> 3);
    const int acp = (tid & 7) * 2;

    const int total = TT + (L - 1);
    for (int s = 0; s < total; ++s) {
        const int mode = (s < TT) ? 0 : 1;
        const int t = mode ? (s - TT) : s;

        const float* hin;
        float* hout;
        const uint2* hs_in;
        uint2* hs_out;
        const uint2* Ws;
        const float* bias;
        int Kdim;
        if (mode == 0) {
            hin = g_h[t & 1];
            hout = (t == TT - 1) ? g_hist : g_h[(t + 1) & 1];
            hs_in = (t & 1) ? g_hs1 : g_hs0;
            hs_out = (t & 1) ? g_hs0 : g_hs1;
            Ws = g_Wenc_s; bias = g_benc; Kdim = KENC;
        } else {
            hin = g_hist + (size_t)t * BB * HH;
            hout = g_hist + (size_t)(t + 1) * BB * HH;
            hs_in = (t & 1) ? g_hs1 : g_hs0;
            hs_out = (t & 1) ? g_hs0 : g_hs1;
            Ws = g_Wdec_s; bias = g_bdec; Kdim = KDEC;
        }
        const int NC = Kdim / 32;

        float acc[2][4][4];
        #pragma unroll
        for (int a = 0; a < 2; ++a)
            #pragma unroll
            for (int b = 0; b < 4; ++b)
                #pragma unroll
                for (int q = 0; q < 4; ++q) acc[a][b][q] = 0.0f;

        // ---- issue chunk cc into buffer cc%3 (no-op past the end) ----
        auto issue = [&](int cc) {
            if (cc >= NC) { asm volatile("cp.async.commit_group;" ::: "memory"); return; }
            const int kp0 = cc * 16;
            const uint32_t bb_ = sbase + (uint32_t)(cc % 3) * (BUF_U64 * 8);
            #pragma unroll
            for (int u = 0; u < 2; ++u) {
                int r = arow + u * 32;
                const void* gp = (kp0 < HH / 2)
                    ? (const void*)&hs_in[(size_t)(m0 + r) * (HH / 2) + kp0 + acp]
                    : (const void*)&g_xs[(size_t)(m0 + r) * (TT * II / 2) + (size_t)t * (II / 2) + (kp0 - HH / 2) + acp];
                cp16(bb_ + (uint32_t)(r * SPITCH + acp) * 8, gp);
            }
            #pragma unroll
            for (int u = 0; u < 4; ++u) {
                int f = tid + u * 256;
                int n = f >> 3, cp = (f & 7) * 2;
                size_t row = (size_t)((n >> 5) * HH + j0 + (n & 31));
                cp16(bb_ + (uint32_t)((64 + n) * SPITCH + cp) * 8,
                     &Ws[row * (Kdim / 2) + kp0 + cp]);
            }
            asm volatile("cp.async.commit_group;" ::: "memory");
        };

        issue(0);
        issue(1);
        for (int c = 0; c < NC; ++c) {
            if (c + 1 < NC) {
                asm volatile("cp.async.wait_group 1;" ::: "memory");
            } else {
                asm volatile("cp.async.wait_group 0;" ::: "memory");
            }
            __syncthreads();   // compute(c-1) done CTA-wide; group c landed
            issue(c + 2);      // buf (c+2)%3 == (c-1)%3 — free since the sync above

            const uint2* A = sm + (size_t)(c % 3) * BUF_U64;      // rows 0..63
            const uint2* Bm = A + 64 * SPITCH;                    // rows 0..127
            #pragma unroll
            for (int kss = 0; kss < 2; ++kss) {
                const int ks = kss ^ (wid & 1);   // stagger: half the warps reverse order
                const int ko = ks * 8;
                uint2 qa[2][4], qb[4][2];
                #pragma unroll
                for (int mt = 0; mt < 2; ++mt) {
                    int ar = wm * 32 + mt * 16 + lr;
                    qa[mt][0] = A[ar * SPITCH + ko + lc];
                    qa[mt][1] = A[(ar + 8) * SPITCH + ko + lc];
                    qa[mt][2] = A[ar * SPITCH + ko + lc + 4];
                    qa[mt][3] = A[(ar + 8) * SPITCH + ko + lc + 4];
                }
                #pragma unroll
                for (int g = 0; g < 4; ++g) {
                    int bn = g * 32 + jb * 8 + lr;
                    qb[g][0] = Bm[bn * SPITCH + ko + lc];
                    qb[g][1] = Bm[bn * SPITCH + ko + lc + 4];
                }
                // term-major: same-acc mma distance = 8
                #pragma unroll
                for (int g = 0; g < 4; ++g)
                    #pragma unroll
                    for (int mt = 0; mt < 2; ++mt)
                        mmab(acc[mt][g], qa[mt][0].x, qa[mt][1].x, qa[mt][2].x, qa[mt][3].x,
                             qb[g][0].x, qb[g][1].x);          // hi*hi
                #pragma unroll
                for (int g = 0; g < 4; ++g)
                    #pragma unroll
                    for (int mt = 0; mt < 2; ++mt)
                        mmab(acc[mt][g], qa[mt][0].x, qa[mt][1].x, qa[mt][2].x, qa[mt][3].x,
                             qb[g][0].y, qb[g][1].y);          // hi*lo
                #pragma unroll
                for (int g = 0; g < 4; ++g)
                    #pragma unroll
                    for (int mt = 0; mt < 2; ++mt)
                        mmab(acc[mt][g], qa[mt][0].y, qa[mt][1].y, qa[mt][2].y, qa[mt][3].y,
                             qb[g][0].x, qb[g][1].x);          // lo*hi
            }
        }

        // ---- GRU epilogue ----
        #pragma unroll
        for (int mt = 0; mt < 2; ++mt) {
            #pragma unroll
            for (int half = 0; half < 2; ++half) {
                int m = m0 + wm * 32 + mt * 16 + lr + half * 8;
                int j = j0 + jb * 8 + 2 * lc;
                float2 br = *reinterpret_cast<const float2*>(&bias[j]);
                float2 bz = *reinterpret_cast<const float2*>(&bias[HH + j]);
                float2 bi = *reinterpret_cast<const float2*>(&bias[2 * HH + j]);
                float2 bh = *reinterpret_cast<const float2*>(&bias[3 * HH + j]);
                float2 hp = *reinterpret_cast<const float2*>(&hin[(size_t)m * HH + j]);
                int i0 = half * 2, i1 = half * 2 + 1;
                float r0 = sigmoidf_(acc[mt][0][i0] + br.x);
                float r1 = sigmoidf_(acc[mt][0][i1] + br.y);
                float z0 = sigmoidf_(acc[mt][1][i0] + bz.x);
                float z1 = sigmoidf_(acc[mt][1][i1] + bz.y);
                float n0 = tanhf(acc[mt][2][i0] + bi.x + r0 * (acc[mt][3][i0] + bh.x));
                float n1 = tanhf(acc[mt][2][i1] + bi.y + r1 * (acc[mt][3][i1] + bh.y));
                float2 o;
                o.x = (1.0f - z0) * n0 + z0 * hp.x;
                o.y = (1.0f - z1) * n1 + z1 * hp.y;
                *reinterpret_cast<float2*>(&hout[(size_t)m * HH + j]) = o;
                hs_out[(size_t)m * (HH / 2) + (j >> 1)] = split2(o.x, o.y);
            }
        }

        // ---- grid barrier: release arrive + acquire poll ----
        __threadfence();
        __syncthreads();
        if (tid == 0) {
            atomicAdd(&g_bar, 1u);
            const unsigned target = (unsigned)NCTA * (unsigned)(s + 1);
            unsigned v;
            do {
                asm volatile("ld.acquire.gpu.global.u32 %0, [%1];"
                             : "=r"(v) : "l"(&g_bar) : "memory");
                if (v < target) __nanosleep(64);
            } while (v < target);
        }
        __syncthreads();
    }
}

// ---------------- final projection (SIMT, one launch) ----------------
#define PBK 32
__global__ __launch_bounds__(256) void k_proj(float* __restrict__ out, int L,
                                              const float* __restrict__ Wo,
                                              const float* __restrict__ bo) {
    __shared__ float As[64][PBK + 1];
    __shared__ float Bs[64][PBK + 1];
    const int row0 = blockIdx.x * 64;
    const int tid = threadIdx.x;
    const int tx = tid & 15, ty = tid >> 4;
    float acc[4][4] = {};
    for (int k0 = 0; k0 < HH; k0 += PBK) {
        #pragma unroll
        for (int u = 0; u < 2; ++u) {
            int f = tid + u * 256; int r = f >> 3; int c = (f & 7) * 4;
            float4 v = *reinterpret_cast<const float4*>(&g_hist[(size_t)(row0 + r) * HH + k0 + c]);
            As[r][c] = v.x; As[r][c + 1] = v.y; As[r][c + 2] = v.z; As[r][c + 3] = v.w;
        }
        #pragma unroll
        for (int u = 0; u < 2; ++u) {
            int f = tid + u * 256; int r = f >> 3; int c = (f & 7) * 4;
            float4 v = *reinterpret_cast<const float4*>(&Wo[(size_t)r * HH + k0 + c]);
            Bs[r][c] = v.x; Bs[r][c + 1] = v.y; Bs[r][c + 2] = v.z; Bs[r][c + 3] = v.w;
        }
        __syncthreads();
        #pragma unroll 8
        for (int kk = 0; kk < PBK; ++kk) {
            float a[4], b[4];
            #pragma unroll
            for (int i = 0; i < 4; ++i) a[i] = As[ty + 16 * i][kk];
            #pragma unroll
            for (int jn = 0; jn < 4; ++jn) b[jn] = Bs[tx + 16 * jn][kk];
            #pragma unroll
            for (int i = 0; i < 4; ++i)
                #pragma unroll
                for (int jn = 0; jn < 4; ++jn) acc[i][jn] += a[i] * b[jn];
        }
        __syncthreads();
    }
    #pragma unroll
    for (int i = 0; i < 4; ++i) {
        int row = row0 + ty + 16 * i;
        int tt = row >> 9;
        int b = row & (BB - 1);
        #pragma unroll
        for (int jn = 0; jn < 4; ++jn) {
            int o = tx + 16 * jn;
            out[((size_t)b * L + tt) * OO + o] = acc[i][jn] + bo[o];
        }
    }
}

// ---------------- host launcher ----------------
extern "C" void kernel_launch(void* const* d_in, const int* in_sizes, int n_in,
                              void* d_out, int out_size) {
    (void)n_in; (void)in_sizes;
    const float* input = (const float*)d_in[0];
    const float* Wih   = (const float*)d_in[1];
    const float* Whh   = (const float*)d_in[2];
    const float* bih   = (const float*)d_in[3];
    const float* bhh   = (const float*)d_in[4];
    const float* Wo    = (const float*)d_in[5];
    const float* bo    = (const float*)d_in[6];
    float* out = (float*)d_out;

    int L = out_size / (BB * OO);
    if (L > LMAX) L = LMAX;
    if (L < 1) L = 1;

    cudaFuncSetAttribute(k_gru, cudaFuncAttributeMaxDynamicSharedMemorySize, SMEM_BYTES);

    k_zero_h0<<<(BB * HH + 255) / 256, 256>>>();
    k_prep_dec<<<(4 * HH * (KDEC / 2) + 255) / 256, 256>>>(Whh, Wih, Wo);
    k_prep_enc<<<(4 * HH * (KENC / 2) + 255) / 256, 256>>>(Whh, Wih);
    k_prep_x<<<(int)(((size_t)BB * TT * II / 2 + 255) / 256), 256>>>(input);
    k_prep_bias<<<(4 * HH + 255) / 256, 256>>>(bih, bhh, Wih, bo);

    dim3 grid(BB / 64, HH / 32);   // (8, 16) = 128 CTAs, all resident
    k_gru<<<grid, STEP_THREADS, SMEM_BYTES>>>(L);

    k_proj<<<L * (BB / 64), 256>>>(out, L, Wo, bo);
}

// round 17
// speedup vs baseline: 1.0690x; 1.0690x over previous
#include <cuda_runtime.h>
#include <cstdint>
#include <cstddef>

// ---------------- problem constants ----------------
#define BB 512
#define TT 128
#define II 64
#define HH 512
#define OO 64
#define LMAX 300
#define KENC 576   // [h(512) | x(64)]
#define KDEC 512

#define NCTA 128   // persistent grid size (8 x 16)

// ---------------- device scratch ----------------
__device__ float g_h[2][BB * HH];                   // fp32 encoder ping-pong
__device__ float g_hist[(size_t)LMAX * BB * HH];    // fp32 decoder hidden history
__device__ uint2 g_hs0[BB * HH / 2];                // split-h ping-pong (bf16 hi|lo pairs)
__device__ uint2 g_hs1[BB * HH / 2];
__device__ uint2 g_Wdec_s[4 * HH * KDEC / 2];
__device__ uint2 g_Wenc_s[4 * HH * KENC / 2];
__device__ uint2 g_xs[(size_t)BB * TT * II / 2];
__device__ float g_bdec[4 * HH];
__device__ float g_benc[4 * HH];
__device__ unsigned g_bar;                          // grid barrier (zeroed every launch)

// ---------------- helpers ----------------
__device__ __forceinline__ float sigmoidf_(float x) { return 1.0f / (1.0f + __expf(-x)); }

__device__ __forceinline__ uint2 split2(float v0, float v1) {
    uint32_t hi;
    asm("cvt.rn.bf16x2.f32 %0, %1, %2;" : "=r"(hi) : "f"(v1), "f"(v0));
    float h0 = __uint_as_float(hi << 16);
    float h1 = __uint_as_float(hi & 0xFFFF0000u);
    uint32_t lo;
    asm("cvt.rn.bf16x2.f32 %0, %1, %2;" : "=r"(lo) : "f"(v1 - h1), "f"(v0 - h0));
    return make_uint2(hi, lo);
}

__device__ __forceinline__ void mmab(float d[4], uint32_t a0, uint32_t a1, uint32_t a2,
                                     uint32_t a3, uint32_t b0, uint32_t b1) {
    asm volatile(
        "mma.sync.aligned.m16n8k16.row.col.f32.bf16.bf16.f32 "
        "{%0,%1,%2,%3},{%4,%5,%6,%7},{%8,%9},{%0,%1,%2,%3};"
        : "+f"(d[0]), "+f"(d[1]), "+f"(d[2]), "+f"(d[3])
        : "r"(a0), "r"(a1), "r"(a2), "r"(a3), "r"(b0), "r"(b1));
}

__device__ __forceinline__ void cp16(uint32_t saddr, const void* gaddr) {
    asm volatile("cp.async.cg.shared.global [%0], [%1], 16;"
                 :: "r"(saddr), "l"(gaddr) : "memory");
}
__device__ __forceinline__ uint32_t smem_u32_(const void* p) {
    uint32_t a;
    asm("{ .reg .u64 t; cvta.to.shared.u64 t, %1; cvt.u32.u64 %0, t; }" : "=r"(a) : "l"(p));
    return a;
}

// ---------------- prep kernels ----------------
__global__ void k_zero_h0() {
    int i = blockIdx.x * blockDim.x + threadIdx.x;
    if (i < BB * HH) g_h[0][i] = 0.0f;
    if (i < BB * HH / 2) g_hs0[i] = make_uint2(0u, 0u);
    if (i == 0) g_bar = 0u;
}

__global__ void k_prep_dec(const float* __restrict__ Whh, const float* __restrict__ Wih,
                           const float* __restrict__ Wo) {
    int idx = blockIdx.x * blockDim.x + threadIdx.x;
    if (idx >= 4 * HH * (KDEC / 2)) return;
    int row = idx / (KDEC / 2);
    int kp = idx % (KDEC / 2);
    float v[2];
    #pragma unroll
    for (int e = 0; e < 2; ++e) {
        int k = 2 * kp + e;
        if (row < 3 * HH) {
            float s = 0.0f;
            const float* wr = Wih + (size_t)row * II;
            #pragma unroll 8
            for (int o = 0; o < II; ++o) s += wr[o] * Wo[(size_t)o * HH + k];
            v[e] = (row < 2 * HH) ? (Whh[(size_t)row * HH + k] + s) : s;
        } else {
            v[e] = Whh[(size_t)(row - HH) * HH + k];
        }
    }
    g_Wdec_s[idx] = split2(v[0], v[1]);
}

__global__ void k_prep_enc(const float* __restrict__ Whh, const float* __restrict__ Wih) {
    int idx = blockIdx.x * blockDim.x + threadIdx.x;
    if (idx >= 4 * HH * (KENC / 2)) return;
    int row = idx / (KENC / 2);
    int kp = idx % (KENC / 2);
    int g = row >> 9, j = row & (HH - 1);
    float v[2];
    #pragma unroll
    for (int e = 0; e < 2; ++e) {
        int k = 2 * kp + e;
        float val = 0.0f;
        if (g == 0) val = (k < HH) ? Whh[(size_t)j * HH + k]            : Wih[(size_t)j * II + (k - HH)];
        if (g == 1) val = (k < HH) ? Whh[(size_t)(HH + j) * HH + k]     : Wih[(size_t)(HH + j) * II + (k - HH)];
        if (g == 2) val = (k < HH) ? 0.0f                               : Wih[(size_t)(2 * HH + j) * II + (k - HH)];
        if (g == 3) val = (k < HH) ? Whh[(size_t)(2 * HH + j) * HH + k] : 0.0f;
        v[e] = val;
    }
    g_Wenc_s[idx] = split2(v[0], v[1]);
}

__global__ void k_prep_x(const float* __restrict__ input) {
    size_t idx = (size_t)blockIdx.x * blockDim.x + threadIdx.x;
    if (idx >= (size_t)BB * TT * II / 2) return;
    g_xs[idx] = split2(input[2 * idx], input[2 * idx + 1]);
}

__global__ void k_prep_bias(const float* __restrict__ bih, const float* __restrict__ bhh,
                            const float* __restrict__ Wih, const float* __restrict__ bo) {
    int idx = blockIdx.x * blockDim.x + threadIdx.x;
    if (idx >= 4 * HH) return;
    int g = idx >> 9, j = idx & (HH - 1);
    float be;
    if (g == 0) be = bih[j] + bhh[j];
    else if (g == 1) be = bih[HH + j] + bhh[HH + j];
    else if (g == 2) be = bih[2 * HH + j];
    else be = bhh[2 * HH + j];
    g_benc[idx] = be;
    float bd;
    if (g < 3) {
        int r = g * HH + j;
        float s = 0.0f;
        const float* wr = Wih + (size_t)r * II;
        #pragma unroll 8
        for (int o = 0; o < II; ++o) s += wr[o] * bo[o];
        bd = bih[r] + s + ((g < 2) ? bhh[r] : 0.0f);
    } else {
        bd = bhh[2 * HH + j];
    }
    g_bdec[idx] = bd;
}

// ---------------- persistent fused GRU ----------------
// grid (8, 16) = 128 CTAs, 1/SM. CTA tile 64 batch x (4 gates x 32 j).
// 3-stage cp.async pipeline; SMSP-correct warp stagger ((wid>>2)&1) so the two
// warps sharing each SMSP are anti-phased LDS vs MMA; release-red / acquire-poll
// grid barrier between steps.
#define STEP_THREADS 256
#define SPITCH 20                                      // u64 per smem row
#define ROWS_BUF 192                                   // 64 A rows + 128 B rows
#define BUF_U64 (ROWS_BUF * SPITCH)
#define SMEM_BYTES (3 * BUF_U64 * 8)                   // 92160

__global__ __launch_bounds__(STEP_THREADS, 1) void k_gru(int L) {
    extern __shared__ __align__(16) uint2 sm[];        // [3][192][SPITCH]

    const int tid = threadIdx.x, lane = tid & 31, wid = tid >> 5;
    const int wm = wid >> 2, jb = wid & 3;
    const int m0 = blockIdx.x * 64, j0 = blockIdx.y * 32;
    const int lr = lane >> 2, lc = lane & 3;
    const uint32_t sbase = smem_u32_(sm);

    const int arow = (tid >> 3);
    const int acp = (tid & 7) * 2;

    const int total = TT + (L - 1);
    for (int s = 0; s < total; ++s) {
        const int mode = (s < TT) ? 0 : 1;
        const int t = mode ? (s - TT) : s;

        const float* hin;
        float* hout;
        const uint2* hs_in;
        uint2* hs_out;
        const uint2* Ws;
        const float* bias;
        int Kdim;
        if (mode == 0) {
            hin = g_h[t & 1];
            hout = (t == TT - 1) ? g_hist : g_h[(t + 1) & 1];
            hs_in = (t & 1) ? g_hs1 : g_hs0;
            hs_out = (t & 1) ? g_hs0 : g_hs1;
            Ws = g_Wenc_s; bias = g_benc; Kdim = KENC;
        } else {
            hin = g_hist + (size_t)t * BB * HH;
            hout = g_hist + (size_t)(t + 1) * BB * HH;
            hs_in = (t & 1) ? g_hs1 : g_hs0;
            hs_out = (t & 1) ? g_hs0 : g_hs1;
            Ws = g_Wdec_s; bias = g_bdec; Kdim = KDEC;
        }
        const int NC = Kdim / 32;

        float acc[2][4][4];
        #pragma unroll
        for (int a = 0; a < 2; ++a)
            #pragma unroll
            for (int b = 0; b < 4; ++b)
                #pragma unroll
                for (int q = 0; q < 4; ++q) acc[a][b][q] = 0.0f;

        // ---- issue chunk cc into buffer cc%3 (no-op past the end) ----
        auto issue = [&](int cc) {
            if (cc >= NC) { asm volatile("cp.async.commit_group;" ::: "memory"); return; }
            const int kp0 = cc * 16;
            const uint32_t bb_ = sbase + (uint32_t)(cc % 3) * (BUF_U64 * 8);
            #pragma unroll
            for (int u = 0; u < 2; ++u) {
                int r = arow + u * 32;
                const void* gp = (kp0 < HH / 2)
                    ? (const void*)&hs_in[(size_t)(m0 + r) * (HH / 2) + kp0 + acp]
                    : (const void*)&g_xs[(size_t)(m0 + r) * (TT * II / 2) + (size_t)t * (II / 2) + (kp0 - HH / 2) + acp];
                cp16(bb_ + (uint32_t)(r * SPITCH + acp) * 8, gp);
            }
            #pragma unroll
            for (int u = 0; u < 4; ++u) {
                int f = tid + u * 256;
                int n = f >> 3, cp = (f & 7) * 2;
                size_t row = (size_t)((n >> 5) * HH + j0 + (n & 31));
                cp16(bb_ + (uint32_t)((64 + n) * SPITCH + cp) * 8,
                     &Ws[row * (Kdim / 2) + kp0 + cp]);
            }
            asm volatile("cp.async.commit_group;" ::: "memory");
        };

        issue(0);
        issue(1);
        for (int c = 0; c < NC; ++c) {
            if (c + 1 < NC) {
                asm volatile("cp.async.wait_group 1;" ::: "memory");
            } else {
                asm volatile("cp.async.wait_group 0;" ::: "memory");
            }
            __syncthreads();   // compute(c-1) done CTA-wide; group c landed

            const uint2* A = sm + (size_t)(c % 3) * BUF_U64;      // rows 0..63
            const uint2* Bm = A + 64 * SPITCH;                    // rows 0..127
            #pragma unroll
            for (int kss = 0; kss < 2; ++kss) {
                const int ks = kss ^ ((wid >> 2) & 1);  // anti-phase the two warps per SMSP
                const int ko = ks * 8;
                uint2 qa[2][4];
                #pragma unroll
                for (int mt = 0; mt < 2; ++mt) {
                    int ar = wm * 32 + mt * 16 + lr;
                    qa[mt][0] = A[ar * SPITCH + ko + lc];
                    qa[mt][1] = A[(ar + 8) * SPITCH + ko + lc];
                    qa[mt][2] = A[ar * SPITCH + ko + lc + 4];
                    qa[mt][3] = A[(ar + 8) * SPITCH + ko + lc + 4];
                }
                #pragma unroll
                for (int g = 0; g < 4; ++g) {
                    int bn = g * 32 + jb * 8 + lr;
                    uint2 p0 = Bm[bn * SPITCH + ko + lc];
                    uint2 p1 = Bm[bn * SPITCH + ko + lc + 4];
                    #pragma unroll
                    for (int mt = 0; mt < 2; ++mt) {
                        mmab(acc[mt][g], qa[mt][0].x, qa[mt][1].x, qa[mt][2].x, qa[mt][3].x,
                             p0.x, p1.x);
                        mmab(acc[mt][g], qa[mt][0].x, qa[mt][1].x, qa[mt][2].x, qa[mt][3].x,
                             p0.y, p1.y);
                        mmab(acc[mt][g], qa[mt][0].y, qa[mt][1].y, qa[mt][2].y, qa[mt][3].y,
                             p0.x, p1.x);
                    }
                }
            }
            issue(c + 2);   // buf (c+2)%3 == (c-1)%3 — free since the sync above
        }

        // ---- GRU epilogue ----
        #pragma unroll
        for (int mt = 0; mt < 2; ++mt) {
            #pragma unroll
            for (int half = 0; half < 2; ++half) {
                int m = m0 + wm * 32 + mt * 16 + lr + half * 8;
                int j = j0 + jb * 8 + 2 * lc;
                float2 br = *reinterpret_cast<const float2*>(&bias[j]);
                float2 bz = *reinterpret_cast<const float2*>(&bias[HH + j]);
                float2 bi = *reinterpret_cast<const float2*>(&bias[2 * HH + j]);
                float2 bh = *reinterpret_cast<const float2*>(&bias[3 * HH + j]);
                float2 hp = *reinterpret_cast<const float2*>(&hin[(size_t)m * HH + j]);
                int i0 = half * 2, i1 = half * 2 + 1;
                float r0 = sigmoidf_(acc[mt][0][i0] + br.x);
                float r1 = sigmoidf_(acc[mt][0][i1] + br.y);
                float z0 = sigmoidf_(acc[mt][1][i0] + bz.x);
                float z1 = sigmoidf_(acc[mt][1][i1] + bz.y);
                float n0 = tanhf(acc[mt][2][i0] + bi.x + r0 * (acc[mt][3][i0] + bh.x));
                float n1 = tanhf(acc[mt][2][i1] + bi.y + r1 * (acc[mt][3][i1] + bh.y));
                float2 o;
                o.x = (1.0f - z0) * n0 + z0 * hp.x;
                o.y = (1.0f - z1) * n1 + z1 * hp.y;
                *reinterpret_cast<float2*>(&hout[(size_t)m * HH + j]) = o;
                hs_out[(size_t)m * (HH / 2) + (j >> 1)] = split2(o.x, o.y);
            }
        }

        // ---- grid barrier: release red.add arrive + acquire poll ----
        __syncthreads();
        if (tid == 0) {
            asm volatile("red.release.gpu.global.add.u32 [%0], %1;"
                         :: "l"(&g_bar), "r"(1u) : "memory");
            const unsigned target = (unsigned)NCTA * (unsigned)(s + 1);
            unsigned v;
            do {
                asm volatile("ld.acquire.gpu.global.u32 %0, [%1];"
                             : "=r"(v) : "l"(&g_bar) : "memory");
                if (v < target) __nanosleep(64);
            } while (v < target);
        }
        __syncthreads();
    }
}

// ---------------- final projection (SIMT, one launch) ----------------
#define PBK 32
__global__ __launch_bounds__(256) void k_proj(float* __restrict__ out, int L,
                                              const float* __restrict__ Wo,
                                              const float* __restrict__ bo) {
    __shared__ float As[64][PBK + 1];
    __shared__ float Bs[64][PBK + 1];
    const int row0 = blockIdx.x * 64;
    const int tid = threadIdx.x;
    const int tx = tid & 15, ty = tid >> 4;
    float acc[4][4] = {};
    for (int k0 = 0; k0 < HH; k0 += PBK) {
        #pragma unroll
        for (int u = 0; u < 2; ++u) {
            int f = tid + u * 256; int r = f >> 3; int c = (f & 7) * 4;
            float4 v = *reinterpret_cast<const float4*>(&g_hist[(size_t)(row0 + r) * HH + k0 + c]);
            As[r][c] = v.x; As[r][c + 1] = v.y; As[r][c + 2] = v.z; As[r][c + 3] = v.w;
        }
        #pragma unroll
        for (int u = 0; u < 2; ++u) {
            int f = tid + u * 256; int r = f >> 3; int c = (f & 7) * 4;
            float4 v = *reinterpret_cast<const float4*>(&Wo[(size_t)r * HH + k0 + c]);
            Bs[r][c] = v.x; Bs[r][c + 1] = v.y; Bs[r][c + 2] = v.z; Bs[r][c + 3] = v.w;
        }
        __syncthreads();
        #pragma unroll 8
        for (int kk = 0; kk < PBK; ++kk) {
            float a[4], b[4];
            #pragma unroll
            for (int i = 0; i < 4; ++i) a[i] = As[ty + 16 * i][kk];
            #pragma unroll
            for (int jn = 0; jn < 4; ++jn) b[jn] = Bs[tx + 16 * jn][kk];
            #pragma unroll
            for (int i = 0; i < 4; ++i)
                #pragma unroll
                for (int jn = 0; jn < 4; ++jn) acc[i][jn] += a[i] * b[jn];
        }
        __syncthreads();
    }
    #pragma unroll
    for (int i = 0; i < 4; ++i) {
        int row = row0 + ty + 16 * i;
        int tt = row >> 9;
        int b = row & (BB - 1);
        #pragma unroll
        for (int jn = 0; jn < 4; ++jn) {
            int o = tx + 16 * jn;
            out[((size_t)b * L + tt) * OO + o] = acc[i][jn] + bo[o];
        }
    }
}

// ---------------- host launcher ----------------
extern "C" void kernel_launch(void* const* d_in, const int* in_sizes, int n_in,
                              void* d_out, int out_size) {
    (void)n_in; (void)in_sizes;
    const float* input = (const float*)d_in[0];
    const float* Wih   = (const float*)d_in[1];
    const float* Whh   = (const float*)d_in[2];
    const float* bih   = (const float*)d_in[3];
    const float* bhh   = (const float*)d_in[4];
    const float* Wo    = (const float*)d_in[5];
    const float* bo    = (const float*)d_in[6];
    float* out = (float*)d_out;

    int L = out_size / (BB * OO);
    if (L > LMAX) L = LMAX;
    if (L < 1) L = 1;

    cudaFuncSetAttribute(k_gru, cudaFuncAttributeMaxDynamicSharedMemorySize, SMEM_BYTES);

    k_zero_h0<<<(BB * HH + 255) / 256, 256>>>();
    k_prep_dec<<<(4 * HH * (KDEC / 2) + 255) / 256, 256>>>(Whh, Wih, Wo);
    k_prep_enc<<<(4 * HH * (KENC / 2) + 255) / 256, 256>>>(Whh, Wih);
    k_prep_x<<<(int)(((size_t)BB * TT * II / 2 + 255) / 256), 256>>>(input);
    k_prep_bias<<<(4 * HH + 255) / 256, 256>>>(bih, bhh, Wih, bo);

    dim3 grid(BB / 64, HH / 32);   // (8, 16) = 128 CTAs, all resident
    k_gru<<<grid, STEP_THREADS, SMEM_BYTES>>>(L);

    k_proj<<<L * (BB / 64), 256>>>(out, L, Wo, bo);
}